// round 16
// baseline (speedup 1.0000x reference)
#include <cuda_runtime.h>
#include <math.h>

#define NROW 8192
#define DIN  512
#define DH   256
#define SLOPE 0.1f
#define CHUNK 16
#define NCHUNK 512   // NROW / CHUNK

// ---------------- zeroed-every-replay scratch (one memset region) ----------------
#define Z_BYTES ((4 * NROW + 1) * 4)
__device__ __align__(128) unsigned char g_zmem[Z_BYTES];
#define G_S1   ((float*)g_zmem)
#define G_S2   (((float*)g_zmem) + NROW)
#define G_RANK (((int*)g_zmem) + 2 * NROW)
#define G_DONE (((int*)g_zmem) + 3 * NROW)
#define G_MAXU ((unsigned*)(((int*)g_zmem) + 4 * NROW))

// ---------------- other scratch ----------------
__device__ float    g_h[NROW * DH];                 // 8 MB
__device__ float    g_pj[NROW], g_qj[NROW];         // original order
__device__ float    g_s2s[NROW];                    // sorted s2
__device__ int      g_perm[NROW];                   // sorted -> original
__device__ float    g_ps[NROW], g_qs[NROW];         // sorted order
__device__ double   g_chPT[DH * NCHUNK], g_chQT[DH * NCHUNK];   // TRANSPOSED [c][cc]
__device__ double   g_chSp[NCHUNK], g_chSq[NCHUNK];
__device__ double   g_TotP[DH];
__device__ double   g_SpTot;
__device__ float    g_SufP[(NROW + 1) * DH];        // fp32 suffix of p*h (sorted)
__device__ float    g_PreQ[(NROW + 1) * DH];        // fp32 prefix of q*h (sorted)
__device__ double   g_SpSuf[NROW + 1], g_SqPre[NROW + 1];

// ordered-uint encoding of float for atomicMax (zero-bytes == -inf)
__device__ __forceinline__ unsigned f2ord(float x) {
    unsigned u = __float_as_uint(x);
    return (u & 0x80000000u) ? ~u : (u | 0x80000000u);
}
__device__ __forceinline__ float ord2f(unsigned u) {
    unsigned b = (u & 0x80000000u) ? (u & 0x7FFFFFFFu) : ~u;
    return __uint_as_float(b);
}

// packed f32x2 helpers (PTX-only fma.rn.f32x2; works at sm_100 base target)
__device__ __forceinline__ unsigned long long pack2(float v) {
    unsigned long long r;
    asm("mov.b64 %0, {%1, %1};" : "=l"(r) : "r"(__float_as_uint(v)));
    return r;
}
__device__ __forceinline__ unsigned long long fma2(unsigned long long a,
                                                   unsigned long long b,
                                                   unsigned long long c) {
    unsigned long long d;
    asm("fma.rn.f32x2 %0, %1, %2, %3;" : "=l"(d) : "l"(a), "l"(b), "l"(c));
    return d;
}
__device__ __forceinline__ void unpack2(unsigned long long v, float& lo, float& hi) {
    unsigned a, b;
    asm("mov.b64 {%0, %1}, %2;" : "=r"(a), "=r"(b) : "l"(v));
    lo = __uint_as_float(a); hi = __uint_as_float(b);
}

// ---------------- K1: h = doc@W + W_b (fp32x2 SGEMM 128x64) + fused s1/s2 partials ----------------
__global__ __launch_bounds__(256, 2) void k_gemm(const float* __restrict__ doc,
                                                 const float* __restrict__ W,
                                                 const float* __restrict__ Wb,
                                                 const float* __restrict__ a) {
    __shared__ float As[2][16][128];   // [buf][k][m]
    __shared__ float Bs[2][16][64];    // [buf][k][n]
    const int bm = blockIdx.x * 128;
    const int bn = blockIdx.y * 64;
    const int tid = threadIdx.x;
    const int tr = tid >> 4, tc = tid & 15;   // thread tile 8m x 4n
    const int ar0 = tid >> 2,          ac0 = (tid & 3) << 2;
    const int ar1 = (tid + 256) >> 2,  ac1 = ((tid + 256) & 3) << 2;
    const int br  = tid >> 4,          bc  = (tid & 15) << 2;

    unsigned long long acc[4][4];
#pragma unroll
    for (int i = 0; i < 4; i++)
#pragma unroll
        for (int j = 0; j < 4; j++) acc[i][j] = 0ull;

    {
        float4 v0 = *(const float4*)&doc[(size_t)(bm + ar0) * DIN + ac0];
        float4 v1 = *(const float4*)&doc[(size_t)(bm + ar1) * DIN + ac1];
        float4 w  = *(const float4*)&W[(size_t)br * DH + bn + bc];
        As[0][ac0 + 0][ar0] = v0.x; As[0][ac0 + 1][ar0] = v0.y;
        As[0][ac0 + 2][ar0] = v0.z; As[0][ac0 + 3][ar0] = v0.w;
        As[0][ac1 + 0][ar1] = v1.x; As[0][ac1 + 1][ar1] = v1.y;
        As[0][ac1 + 2][ar1] = v1.z; As[0][ac1 + 3][ar1] = v1.w;
        *(float4*)&Bs[0][br][bc] = w;
    }
    __syncthreads();

    const int NSTEP = DIN / 16;   // 32
    for (int step = 0; step < NSTEP; step++) {
        int cur = step & 1;
        float4 v0, v1, w;
        if (step < NSTEP - 1) {
            int k0n = (step + 1) * 16;
            v0 = *(const float4*)&doc[(size_t)(bm + ar0) * DIN + k0n + ac0];
            v1 = *(const float4*)&doc[(size_t)(bm + ar1) * DIN + k0n + ac1];
            w  = *(const float4*)&W[(size_t)(k0n + br) * DH + bn + bc];
        }
#pragma unroll
        for (int kk = 0; kk < 16; kk++) {
            ulonglong2 av0 = *(const ulonglong2*)&As[cur][kk][tr * 8];
            ulonglong2 av1 = *(const ulonglong2*)&As[cur][kk][tr * 8 + 4];
            unsigned long long a64[4] = {av0.x, av0.y, av1.x, av1.y};
            float4 bf = *(const float4*)&Bs[cur][kk][tc * 4];
            unsigned long long bp[4] = {pack2(bf.x), pack2(bf.y), pack2(bf.z), pack2(bf.w)};
#pragma unroll
            for (int mp = 0; mp < 4; mp++)
#pragma unroll
                for (int n = 0; n < 4; n++)
                    acc[mp][n] = fma2(a64[mp], bp[n], acc[mp][n]);
        }
        if (step < NSTEP - 1) {
            int nxt = cur ^ 1;
            As[nxt][ac0 + 0][ar0] = v0.x; As[nxt][ac0 + 1][ar0] = v0.y;
            As[nxt][ac0 + 2][ar0] = v0.z; As[nxt][ac0 + 3][ar0] = v0.w;
            As[nxt][ac1 + 0][ar1] = v1.x; As[nxt][ac1 + 1][ar1] = v1.y;
            As[nxt][ac1 + 2][ar1] = v1.z; As[nxt][ac1 + 3][ar1] = v1.w;
            *(float4*)&Bs[nxt][br][bc] = w;
        }
        __syncthreads();
    }

    float4 wb  = *(const float4*)&Wb[bn + tc * 4];
    float4 a1v = __ldg((const float4*)&a[bn + tc * 4]);
    float4 a2v = __ldg((const float4*)&a[DH + bn + tc * 4]);
    float s1a[8], s2a[8];
#pragma unroll
    for (int mp = 0; mp < 4; mp++) {
        int m0 = bm + tr * 8 + 2 * mp;
        float lo0, hi0, lo1, hi1, lo2, hi2, lo3, hi3;
        unpack2(acc[mp][0], lo0, hi0);
        unpack2(acc[mp][1], lo1, hi1);
        unpack2(acc[mp][2], lo2, hi2);
        unpack2(acc[mp][3], lo3, hi3);
        float4 r0, r1;
        r0.x = lo0 + wb.x; r0.y = lo1 + wb.y; r0.z = lo2 + wb.z; r0.w = lo3 + wb.w;
        r1.x = hi0 + wb.x; r1.y = hi1 + wb.y; r1.z = hi2 + wb.z; r1.w = hi3 + wb.w;
        *(float4*)&g_h[(size_t)m0 * DH + bn + tc * 4] = r0;
        *(float4*)&g_h[(size_t)(m0 + 1) * DH + bn + tc * 4] = r1;
        s1a[2 * mp]     = r0.x * a1v.x + r0.y * a1v.y + r0.z * a1v.z + r0.w * a1v.w;
        s2a[2 * mp]     = r0.x * a2v.x + r0.y * a2v.y + r0.z * a2v.z + r0.w * a2v.w;
        s1a[2 * mp + 1] = r1.x * a1v.x + r1.y * a1v.y + r1.z * a1v.z + r1.w * a1v.w;
        s2a[2 * mp + 1] = r1.x * a2v.x + r1.y * a2v.y + r1.z * a2v.z + r1.w * a2v.w;
    }
#pragma unroll
    for (int r = 0; r < 8; r++) {
        float v1 = s1a[r], v2 = s2a[r];
#pragma unroll
        for (int o = 1; o < 16; o <<= 1) {
            v1 += __shfl_xor_sync(0xffffffffu, v1, o);
            v2 += __shfl_xor_sync(0xffffffffu, v2, o);
        }
        if ((tid & 15) == 0) {
            int row = bm + tr * 8 + r;
            atomicAdd(&G_S1[row], v1);
            atomicAdd(&G_S2[row], v2);
        }
    }
}

// ---------------- K2: fused global-max + rank + scatter (512 blocks, tile=512) ----------------
__global__ void k_ranksc() {
    __shared__ float tile[256];
    int j = blockIdx.x * 256 + threadIdx.x;
    float v = G_S2[j];
    int base = blockIdx.y * 512;
    int rank = 0;
    float mymax = -1e30f;
    for (int t0 = base; t0 < base + 512; t0 += 256) {
        float tv = G_S2[t0 + threadIdx.x];
        tile[threadIdx.x] = tv;
        mymax = fmaxf(mymax, tv);
        __syncthreads();
#pragma unroll 8
        for (int u = 0; u < 256; u++) {
            float w = tile[u];
            rank += (int)((w < v) || (w == v && (t0 + u) < j));
        }
        __syncthreads();
    }
    tile[threadIdx.x] = mymax;
    __syncthreads();
    for (int o = 128; o > 0; o >>= 1) {
        if (threadIdx.x < o) tile[threadIdx.x] = fmaxf(tile[threadIdx.x], tile[threadIdx.x + o]);
        __syncthreads();
    }
    if (threadIdx.x == 0) {
        atomicMax(G_MAXU, f2ord(tile[0]));
        __threadfence();
    }
    __syncthreads();

    atomicAdd(&G_RANK[j], rank);
    __threadfence();
    int old = atomicAdd(&G_DONE[j], 1);
    if (old == 15) {
        __threadfence();
        int r = *(volatile int*)&G_RANK[j];
        float s2m = ord2f(*(volatile unsigned*)G_MAXU);
        float p = expf(v - s2m);
        float q = expf(SLOPE * (v - s2m));
        g_pj[j] = p; g_qj[j] = q;
        g_s2s[r] = v; g_perm[r] = j;
        g_ps[r] = p;  g_qs[r] = q;
    }
}

// ---------------- K3: per-chunk sums of p*h, q*h (transposed store, batched loads) ----------------
__global__ void k_chunk() {
    int cc = blockIdx.x;
    int c = threadIdx.x;
    __shared__ int   sperm[CHUNK];
    __shared__ float sp[CHUNK], sq[CHUNK];
    __shared__ double red[CHUNK];
    if (c < CHUNK) {
        int m = cc * CHUNK + c;
        sperm[c] = g_perm[m];
        sp[c] = g_ps[m];
        sq[c] = g_qs[m];
    }
    __syncthreads();
    float hv[CHUNK];
#pragma unroll
    for (int u = 0; u < CHUNK; u++)
        hv[u] = __ldg(&g_h[(size_t)sperm[u] * DH + c]);
    float ap = 0.f, aq = 0.f;
#pragma unroll
    for (int u = 0; u < CHUNK; u++) {
        ap += sp[u] * hv[u];
        aq += sq[u] * hv[u];
    }
    g_chPT[(size_t)c * NCHUNK + cc] = (double)ap;
    g_chQT[(size_t)c * NCHUNK + cc] = (double)aq;
    if (c < CHUNK) red[c] = (double)sp[c];
    __syncthreads();
#pragma unroll
    for (int o = CHUNK / 2; o > 0; o >>= 1) {
        if (c < o) red[c] += red[c + o];
        __syncthreads();
    }
    if (c == 0) g_chSp[cc] = red[0];
    __syncthreads();
    if (c < CHUNK) red[c] = (double)sq[c];
    __syncthreads();
#pragma unroll
    for (int o = CHUNK / 2; o > 0; o >>= 1) {
        if (c < o) red[c] += red[c + o];
        __syncthreads();
    }
    if (c == 0) g_chSq[cc] = red[0];
}

// ---------------- K4: warp-shuffle scan, coalesced transposed layout ----------------
__global__ __launch_bounds__(NCHUNK) void k_scan() {
    __shared__ double wsum[16];
    __shared__ double woff[17];
    int b = blockIdx.x;   // [0,256)=P col, [256,512)=Q col, 512=chSp, 513=chSq
    int t = threadIdx.x;
    int lane = t & 31, wid = t >> 5;   // 16 warps
    double val;
    if (b < DH)            val = g_chPT[(size_t)b * NCHUNK + t];
    else if (b < 2 * DH)   val = g_chQT[(size_t)(b - DH) * NCHUNK + t];
    else if (b == 2 * DH)  val = g_chSp[t];
    else                   val = g_chSq[t];

    double incl = val;
#pragma unroll
    for (int o = 1; o < 32; o <<= 1) {
        double n = __shfl_up_sync(0xffffffffu, incl, o);
        if (lane >= o) incl += n;
    }
    if (lane == 31) wsum[wid] = incl;
    __syncthreads();
    if (t < 16) {
        double w = wsum[t];
        double wi = w;
#pragma unroll
        for (int o = 1; o < 16; o <<= 1) {
            double n = __shfl_up_sync(0x0000ffffu, wi, o);
            if (t >= o) wi += n;
        }
        woff[t] = wi - w;
        if (t == 15) woff[16] = wi;
    }
    __syncthreads();
    double excl = woff[wid] + incl - val;
    double total = woff[16];

    if (b < DH) {
        g_chPT[(size_t)b * NCHUNK + t] = excl;
        if (t == 0) g_TotP[b] = total;
    } else if (b < 2 * DH) {
        g_chQT[(size_t)(b - DH) * NCHUNK + t] = excl;
    } else if (b == 2 * DH) {
        g_chSp[t] = excl;
        if (t == 0) g_SpTot = total;
    } else {
        g_chSq[t] = excl;
    }
}

// ---------------- K5: fp32 suffix/prefix arrays (front-batched hv loads, MLP=16) ----------------
__global__ void k_prefix() {
    int cc = blockIdx.x;
    int c = threadIdx.x;
    __shared__ int    sperm[CHUNK];
    __shared__ float  sp[CHUNK], sq[CHUNK];
    __shared__ double eP[CHUNK + 1], eQ[CHUNK + 1];
    if (c < CHUNK) {
        int m = cc * CHUNK + c;
        sperm[c] = g_perm[m];
        sp[c] = g_ps[m];
        sq[c] = g_qs[m];
    }
    __syncthreads();
    if (c < 32) {                       // warp 0: shuffle scans of sp and sq (16 lanes live)
        double vp = (c < CHUNK) ? (double)sp[c] : 0.0;
        double vq = (c < CHUNK) ? (double)sq[c] : 0.0;
#pragma unroll
        for (int o = 1; o < CHUNK; o <<= 1) {
            double np = __shfl_up_sync(0xffffffffu, vp, o);
            double nq = __shfl_up_sync(0xffffffffu, vq, o);
            if ((c & 31) >= o) { vp += np; vq += nq; }
        }
        if (c < CHUNK) {
            eP[c + 1] = vp; eQ[c + 1] = vq;
            if (c == 0) { eP[0] = 0.0; eQ[0] = 0.0; }
        }
    }
    __syncthreads();

    // front-batch all 16 h loads (independent; MLP=16)
    float hv[CHUNK];
#pragma unroll
    for (int u = 0; u < CHUNK; u++)
        hv[u] = __ldg(&g_h[(size_t)sperm[u] * DH + c]);

    double rp0 = g_chPT[(size_t)c * NCHUNK + cc];
    double rq0 = g_chQT[(size_t)c * NCHUNK + cc];
    float sufBase = (float)(g_TotP[c] - rp0);
    float preBase = (float)rq0;
    float lp = 0.f, lq = 0.f;
#pragma unroll
    for (int u = 0; u < CHUNK; u++) {
        size_t m = (size_t)cc * CHUNK + u;
        g_SufP[m * DH + c] = sufBase - lp;
        g_PreQ[m * DH + c] = preBase + lq;
        lp += sp[u] * hv[u];
        lq += sq[u] * hv[u];
    }
    if (cc == NCHUNK - 1) {
        g_SufP[(size_t)NROW * DH + c] = sufBase - lp;
        g_PreQ[(size_t)NROW * DH + c] = preBase + lq;
    }
    if (c < CHUNK) {
        int m = cc * CHUNK + c;
        double bSp = g_chSp[cc], bSq = g_chSq[cc], stot = g_SpTot;
        g_SpSuf[m] = stot - (bSp + eP[c]);
        g_SqPre[m] = bSq + eQ[c];
        if (cc == NCHUNK - 1 && c == CHUNK - 1) {
            g_SpSuf[NROW] = stot - (bSp + eP[CHUNK]);
            g_SqPre[NROW] = bSq + eQ[CHUNK];
        }
    }
}

// ---------------- K6: att (268 MB stream, 64 rows/block) + coefs + fused out gather ----------------
__global__ void k_att(float* __restrict__ att, float* __restrict__ out,
                      const float* __restrict__ a_b) {
    __shared__ float sA[64], sB[64], sT[64];
    __shared__ int   sK[64];
    int jx = blockIdx.x, iy = blockIdx.y;
    int i0 = iy * 64;
    int tid = threadIdx.x;
    if (tid < 64) {
        int i = i0 + tid;
        float cb = __ldg(&a_b[0]);
        float s1 = G_S1[i];
        float s2m = ord2f(*G_MAXU);
        float u = s1 + cb + s2m;
        float m = u > 0.f ? u : SLOPE * u;          // exact row max of f(x)
        float alpha = expf(u - m);
        float beta  = expf(SLOPE * u - m);
        float t = -(s1 + cb);                       // x>0  <=>  s2[j] > t
        int lo = 0, hi = NROW;
        while (lo < hi) {
            int mid = (lo + hi) >> 1;
            if (g_s2s[mid] > t) hi = mid; else lo = mid + 1;
        }
        int k = lo;
        double Z = (double)alpha * g_SpSuf[k] + (double)beta * g_SqPre[k];
        float Zf = (float)Z;
        sA[tid] = alpha / Zf;
        sB[tid] = beta / Zf;
        sT[tid] = t;
        sK[tid] = k;
    }
    __syncthreads();
    if (jx == 0) {
        int c = tid;
#pragma unroll 4
        for (int r = 0; r < 64; r++) {
            int i = i0 + r;
            int k = sK[r];
            float v = sA[r] * g_SufP[(size_t)k * DH + c] + sB[r] * g_PreQ[(size_t)k * DH + c];
            out[(size_t)i * DH + c] = v > 0.f ? v : SLOPE * v;
        }
    }
    int j = jx * 1024 + tid * 4;
    float4 p = *(const float4*)&g_pj[j];
    float4 q = *(const float4*)&g_qj[j];
    float4 s = *(const float4*)&G_S2[j];
#pragma unroll 4
    for (int r = 0; r < 64; r++) {
        int i = i0 + r;
        float A = sA[r];
        float B = sB[r];
        float T = sT[r];
        float4 o;
        o.x = s.x > T ? A * p.x : B * q.x;
        o.y = s.y > T ? A * p.y : B * q.y;
        o.z = s.z > T ? A * p.z : B * q.z;
        o.w = s.w > T ? A * p.w : B * q.w;
        __stcs((float4*)&att[(size_t)i * NROW + j], o);
    }
}

// ---------------- launch ----------------
extern "C" void kernel_launch(void* const* d_in, const int* in_sizes, int n_in,
                              void* d_out, int out_size) {
    const float* doc = (const float*)d_in[0];
    const float* W   = (const float*)d_in[1];
    const float* Wb  = (const float*)d_in[2];
    const float* a   = (const float*)d_in[3];
    const float* ab  = (const float*)d_in[4];
    float* out = (float*)d_out;                  // [8192 x 256]
    float* att = out + (size_t)NROW * DH;        // [8192 x 8192]

    static void* zptr = nullptr;
    if (zptr == nullptr) cudaGetSymbolAddress(&zptr, g_zmem);
    cudaMemsetAsync(zptr, 0, Z_BYTES, 0);        // s1,s2,rank,done,s2max := 0

    k_gemm<<<dim3(NROW / 128, DH / 64), 256>>>(doc, W, Wb, a);
    k_ranksc<<<dim3(32, 16), 256>>>();
    k_chunk<<<NCHUNK, 256>>>();
    k_scan<<<2 * DH + 2, NCHUNK>>>();
    k_prefix<<<NCHUNK, 256>>>();
    k_att<<<dim3(NROW / 1024, NROW / 64), 256>>>(att, out, ab);
}

// round 17
// speedup vs baseline: 1.0548x; 1.0548x over previous
#include <cuda_runtime.h>
#include <math.h>

#define NROW 8192
#define DIN  512
#define DH   256
#define SLOPE 0.1f
#define CHUNK 16
#define NCHUNK 512   // NROW / CHUNK

// ---------------- zeroed-every-replay scratch (one memset region) ----------------
#define Z_BYTES ((4 * NROW + 1) * 4)
__device__ __align__(128) unsigned char g_zmem[Z_BYTES];
#define G_S1   ((float*)g_zmem)
#define G_S2   (((float*)g_zmem) + NROW)
#define G_RANK (((int*)g_zmem) + 2 * NROW)
#define G_DONE (((int*)g_zmem) + 3 * NROW)
#define G_MAXU ((unsigned*)(((int*)g_zmem) + 4 * NROW))

// ---------------- other scratch ----------------
__device__ float    g_h[NROW * DH];                 // 8 MB
__device__ float    g_pj[NROW], g_qj[NROW];         // original order
__device__ float    g_s2s[NROW];                    // sorted s2
__device__ int      g_perm[NROW];                   // sorted -> original
__device__ float    g_ps[NROW], g_qs[NROW];         // sorted order
__device__ double   g_chPT[DH * NCHUNK], g_chQT[DH * NCHUNK];   // TRANSPOSED [c][cc]
__device__ double   g_chSp[NCHUNK], g_chSq[NCHUNK];
__device__ double   g_TotP[DH];
__device__ double   g_SpTot;
__device__ float    g_SufP[(NROW + 1) * DH];        // fp32 suffix of p*h (sorted)
__device__ float    g_PreQ[(NROW + 1) * DH];        // fp32 prefix of q*h (sorted)
__device__ double   g_SpSuf[NROW + 1], g_SqPre[NROW + 1];

// ordered-uint encoding of float for atomicMax (zero-bytes == -inf)
__device__ __forceinline__ unsigned f2ord(float x) {
    unsigned u = __float_as_uint(x);
    return (u & 0x80000000u) ? ~u : (u | 0x80000000u);
}
__device__ __forceinline__ float ord2f(unsigned u) {
    unsigned b = (u & 0x80000000u) ? (u & 0x7FFFFFFFu) : ~u;
    return __uint_as_float(b);
}

// packed f32x2 helpers (PTX-only fma.rn.f32x2; works at sm_100 base target)
__device__ __forceinline__ unsigned long long pack2(float v) {
    unsigned long long r;
    asm("mov.b64 %0, {%1, %1};" : "=l"(r) : "r"(__float_as_uint(v)));
    return r;
}
__device__ __forceinline__ unsigned long long fma2(unsigned long long a,
                                                   unsigned long long b,
                                                   unsigned long long c) {
    unsigned long long d;
    asm("fma.rn.f32x2 %0, %1, %2, %3;" : "=l"(d) : "l"(a), "l"(b), "l"(c));
    return d;
}
__device__ __forceinline__ void unpack2(unsigned long long v, float& lo, float& hi) {
    unsigned a, b;
    asm("mov.b64 {%0, %1}, %2;" : "=r"(a), "=r"(b) : "l"(v));
    lo = __uint_as_float(a); hi = __uint_as_float(b);
}

// ---------------- K1: h = doc@W + W_b (fp32x2 SGEMM 128x64) + fused s1/s2 partials ----------------
__global__ __launch_bounds__(256, 2) void k_gemm(const float* __restrict__ doc,
                                                 const float* __restrict__ W,
                                                 const float* __restrict__ Wb,
                                                 const float* __restrict__ a) {
    __shared__ float As[2][16][128];   // [buf][k][m]
    __shared__ float Bs[2][16][64];    // [buf][k][n]
    const int bm = blockIdx.x * 128;
    const int bn = blockIdx.y * 64;
    const int tid = threadIdx.x;
    const int tr = tid >> 4, tc = tid & 15;   // thread tile 8m x 4n
    const int ar0 = tid >> 2,          ac0 = (tid & 3) << 2;
    const int ar1 = (tid + 256) >> 2,  ac1 = ((tid + 256) & 3) << 2;
    const int br  = tid >> 4,          bc  = (tid & 15) << 2;

    unsigned long long acc[4][4];
#pragma unroll
    for (int i = 0; i < 4; i++)
#pragma unroll
        for (int j = 0; j < 4; j++) acc[i][j] = 0ull;

    {
        float4 v0 = *(const float4*)&doc[(size_t)(bm + ar0) * DIN + ac0];
        float4 v1 = *(const float4*)&doc[(size_t)(bm + ar1) * DIN + ac1];
        float4 w  = *(const float4*)&W[(size_t)br * DH + bn + bc];
        As[0][ac0 + 0][ar0] = v0.x; As[0][ac0 + 1][ar0] = v0.y;
        As[0][ac0 + 2][ar0] = v0.z; As[0][ac0 + 3][ar0] = v0.w;
        As[0][ac1 + 0][ar1] = v1.x; As[0][ac1 + 1][ar1] = v1.y;
        As[0][ac1 + 2][ar1] = v1.z; As[0][ac1 + 3][ar1] = v1.w;
        *(float4*)&Bs[0][br][bc] = w;
    }
    __syncthreads();

    const int NSTEP = DIN / 16;   // 32
    for (int step = 0; step < NSTEP; step++) {
        int cur = step & 1;
        float4 v0, v1, w;
        if (step < NSTEP - 1) {
            int k0n = (step + 1) * 16;
            v0 = *(const float4*)&doc[(size_t)(bm + ar0) * DIN + k0n + ac0];
            v1 = *(const float4*)&doc[(size_t)(bm + ar1) * DIN + k0n + ac1];
            w  = *(const float4*)&W[(size_t)(k0n + br) * DH + bn + bc];
        }
#pragma unroll
        for (int kk = 0; kk < 16; kk++) {
            ulonglong2 av0 = *(const ulonglong2*)&As[cur][kk][tr * 8];
            ulonglong2 av1 = *(const ulonglong2*)&As[cur][kk][tr * 8 + 4];
            unsigned long long a64[4] = {av0.x, av0.y, av1.x, av1.y};
            float4 bf = *(const float4*)&Bs[cur][kk][tc * 4];
            unsigned long long bp[4] = {pack2(bf.x), pack2(bf.y), pack2(bf.z), pack2(bf.w)};
#pragma unroll
            for (int mp = 0; mp < 4; mp++)
#pragma unroll
                for (int n = 0; n < 4; n++)
                    acc[mp][n] = fma2(a64[mp], bp[n], acc[mp][n]);
        }
        if (step < NSTEP - 1) {
            int nxt = cur ^ 1;
            As[nxt][ac0 + 0][ar0] = v0.x; As[nxt][ac0 + 1][ar0] = v0.y;
            As[nxt][ac0 + 2][ar0] = v0.z; As[nxt][ac0 + 3][ar0] = v0.w;
            As[nxt][ac1 + 0][ar1] = v1.x; As[nxt][ac1 + 1][ar1] = v1.y;
            As[nxt][ac1 + 2][ar1] = v1.z; As[nxt][ac1 + 3][ar1] = v1.w;
            *(float4*)&Bs[nxt][br][bc] = w;
        }
        __syncthreads();
    }

    float4 wb  = *(const float4*)&Wb[bn + tc * 4];
    float4 a1v = __ldg((const float4*)&a[bn + tc * 4]);
    float4 a2v = __ldg((const float4*)&a[DH + bn + tc * 4]);
    float s1a[8], s2a[8];
#pragma unroll
    for (int mp = 0; mp < 4; mp++) {
        int m0 = bm + tr * 8 + 2 * mp;
        float lo0, hi0, lo1, hi1, lo2, hi2, lo3, hi3;
        unpack2(acc[mp][0], lo0, hi0);
        unpack2(acc[mp][1], lo1, hi1);
        unpack2(acc[mp][2], lo2, hi2);
        unpack2(acc[mp][3], lo3, hi3);
        float4 r0, r1;
        r0.x = lo0 + wb.x; r0.y = lo1 + wb.y; r0.z = lo2 + wb.z; r0.w = lo3 + wb.w;
        r1.x = hi0 + wb.x; r1.y = hi1 + wb.y; r1.z = hi2 + wb.z; r1.w = hi3 + wb.w;
        *(float4*)&g_h[(size_t)m0 * DH + bn + tc * 4] = r0;
        *(float4*)&g_h[(size_t)(m0 + 1) * DH + bn + tc * 4] = r1;
        s1a[2 * mp]     = r0.x * a1v.x + r0.y * a1v.y + r0.z * a1v.z + r0.w * a1v.w;
        s2a[2 * mp]     = r0.x * a2v.x + r0.y * a2v.y + r0.z * a2v.z + r0.w * a2v.w;
        s1a[2 * mp + 1] = r1.x * a1v.x + r1.y * a1v.y + r1.z * a1v.z + r1.w * a1v.w;
        s2a[2 * mp + 1] = r1.x * a2v.x + r1.y * a2v.y + r1.z * a2v.z + r1.w * a2v.w;
    }
#pragma unroll
    for (int r = 0; r < 8; r++) {
        float v1 = s1a[r], v2 = s2a[r];
#pragma unroll
        for (int o = 1; o < 16; o <<= 1) {
            v1 += __shfl_xor_sync(0xffffffffu, v1, o);
            v2 += __shfl_xor_sync(0xffffffffu, v2, o);
        }
        if ((tid & 15) == 0) {
            int row = bm + tr * 8 + r;
            atomicAdd(&G_S1[row], v1);
            atomicAdd(&G_S2[row], v2);
        }
    }
}

// ---------------- K2: fused global-max + rank + scatter (512 blocks, tile=512) ----------------
__global__ void k_ranksc() {
    __shared__ float tile[256];
    int j = blockIdx.x * 256 + threadIdx.x;
    float v = G_S2[j];
    int base = blockIdx.y * 512;
    int rank = 0;
    float mymax = -1e30f;
    for (int t0 = base; t0 < base + 512; t0 += 256) {
        float tv = G_S2[t0 + threadIdx.x];
        tile[threadIdx.x] = tv;
        mymax = fmaxf(mymax, tv);
        __syncthreads();
#pragma unroll 8
        for (int u = 0; u < 256; u++) {
            float w = tile[u];
            rank += (int)((w < v) || (w == v && (t0 + u) < j));
        }
        __syncthreads();
    }
    tile[threadIdx.x] = mymax;
    __syncthreads();
    for (int o = 128; o > 0; o >>= 1) {
        if (threadIdx.x < o) tile[threadIdx.x] = fmaxf(tile[threadIdx.x], tile[threadIdx.x + o]);
        __syncthreads();
    }
    if (threadIdx.x == 0) {
        atomicMax(G_MAXU, f2ord(tile[0]));
        __threadfence();
    }
    __syncthreads();

    atomicAdd(&G_RANK[j], rank);
    __threadfence();
    int old = atomicAdd(&G_DONE[j], 1);
    if (old == 15) {
        __threadfence();
        int r = *(volatile int*)&G_RANK[j];
        float s2m = ord2f(*(volatile unsigned*)G_MAXU);
        float p = expf(v - s2m);
        float q = expf(SLOPE * (v - s2m));
        g_pj[j] = p; g_qj[j] = q;
        g_s2s[r] = v; g_perm[r] = j;
        g_ps[r] = p;  g_qs[r] = q;
    }
}

// ---------------- K3: per-chunk sums of p*h, q*h (transposed store, batched loads) ----------------
__global__ void k_chunk() {
    int cc = blockIdx.x;
    int c = threadIdx.x;
    __shared__ int   sperm[CHUNK];
    __shared__ float sp[CHUNK], sq[CHUNK];
    __shared__ double red[CHUNK];
    if (c < CHUNK) {
        int m = cc * CHUNK + c;
        sperm[c] = g_perm[m];
        sp[c] = g_ps[m];
        sq[c] = g_qs[m];
    }
    __syncthreads();
    float hv[CHUNK];
#pragma unroll
    for (int u = 0; u < CHUNK; u++)
        hv[u] = __ldg(&g_h[(size_t)sperm[u] * DH + c]);
    float ap = 0.f, aq = 0.f;
#pragma unroll
    for (int u = 0; u < CHUNK; u++) {
        ap += sp[u] * hv[u];
        aq += sq[u] * hv[u];
    }
    g_chPT[(size_t)c * NCHUNK + cc] = (double)ap;
    g_chQT[(size_t)c * NCHUNK + cc] = (double)aq;
    if (c < CHUNK) red[c] = (double)sp[c];
    __syncthreads();
#pragma unroll
    for (int o = CHUNK / 2; o > 0; o >>= 1) {
        if (c < o) red[c] += red[c + o];
        __syncthreads();
    }
    if (c == 0) g_chSp[cc] = red[0];
    __syncthreads();
    if (c < CHUNK) red[c] = (double)sq[c];
    __syncthreads();
#pragma unroll
    for (int o = CHUNK / 2; o > 0; o >>= 1) {
        if (c < o) red[c] += red[c + o];
        __syncthreads();
    }
    if (c == 0) g_chSq[cc] = red[0];
}

// ---------------- K4: warp-shuffle scan, coalesced transposed layout ----------------
__global__ __launch_bounds__(NCHUNK) void k_scan() {
    __shared__ double wsum[16];
    __shared__ double woff[17];
    int b = blockIdx.x;   // [0,256)=P col, [256,512)=Q col, 512=chSp, 513=chSq
    int t = threadIdx.x;
    int lane = t & 31, wid = t >> 5;   // 16 warps
    double val;
    if (b < DH)            val = g_chPT[(size_t)b * NCHUNK + t];
    else if (b < 2 * DH)   val = g_chQT[(size_t)(b - DH) * NCHUNK + t];
    else if (b == 2 * DH)  val = g_chSp[t];
    else                   val = g_chSq[t];

    double incl = val;
#pragma unroll
    for (int o = 1; o < 32; o <<= 1) {
        double n = __shfl_up_sync(0xffffffffu, incl, o);
        if (lane >= o) incl += n;
    }
    if (lane == 31) wsum[wid] = incl;
    __syncthreads();
    if (t < 16) {
        double w = wsum[t];
        double wi = w;
#pragma unroll
        for (int o = 1; o < 16; o <<= 1) {
            double n = __shfl_up_sync(0x0000ffffu, wi, o);
            if (t >= o) wi += n;
        }
        woff[t] = wi - w;
        if (t == 15) woff[16] = wi;
    }
    __syncthreads();
    double excl = woff[wid] + incl - val;
    double total = woff[16];

    if (b < DH) {
        g_chPT[(size_t)b * NCHUNK + t] = excl;
        if (t == 0) g_TotP[b] = total;
    } else if (b < 2 * DH) {
        g_chQT[(size_t)(b - DH) * NCHUNK + t] = excl;
    } else if (b == 2 * DH) {
        g_chSp[t] = excl;
        if (t == 0) g_SpTot = total;
    } else {
        g_chSq[t] = excl;
    }
}

// ---------------- K5: fp32 suffix/prefix arrays (front-batched hv loads, MLP=16) ----------------
__global__ void k_prefix() {
    int cc = blockIdx.x;
    int c = threadIdx.x;
    __shared__ int    sperm[CHUNK];
    __shared__ float  sp[CHUNK], sq[CHUNK];
    __shared__ double eP[CHUNK + 1], eQ[CHUNK + 1];
    if (c < CHUNK) {
        int m = cc * CHUNK + c;
        sperm[c] = g_perm[m];
        sp[c] = g_ps[m];
        sq[c] = g_qs[m];
    }
    __syncthreads();
    if (c < 32) {                       // warp 0: shuffle scans of sp and sq (16 lanes live)
        double vp = (c < CHUNK) ? (double)sp[c] : 0.0;
        double vq = (c < CHUNK) ? (double)sq[c] : 0.0;
#pragma unroll
        for (int o = 1; o < CHUNK; o <<= 1) {
            double np = __shfl_up_sync(0xffffffffu, vp, o);
            double nq = __shfl_up_sync(0xffffffffu, vq, o);
            if ((c & 31) >= o) { vp += np; vq += nq; }
        }
        if (c < CHUNK) {
            eP[c + 1] = vp; eQ[c + 1] = vq;
            if (c == 0) { eP[0] = 0.0; eQ[0] = 0.0; }
        }
    }
    __syncthreads();

    // front-batch all 16 h loads (independent; MLP=16)
    float hv[CHUNK];
#pragma unroll
    for (int u = 0; u < CHUNK; u++)
        hv[u] = __ldg(&g_h[(size_t)sperm[u] * DH + c]);

    double rp0 = g_chPT[(size_t)c * NCHUNK + cc];
    double rq0 = g_chQT[(size_t)c * NCHUNK + cc];
    float sufBase = (float)(g_TotP[c] - rp0);
    float preBase = (float)rq0;
    float lp = 0.f, lq = 0.f;
#pragma unroll
    for (int u = 0; u < CHUNK; u++) {
        size_t m = (size_t)cc * CHUNK + u;
        g_SufP[m * DH + c] = sufBase - lp;
        g_PreQ[m * DH + c] = preBase + lq;
        lp += sp[u] * hv[u];
        lq += sq[u] * hv[u];
    }
    if (cc == NCHUNK - 1) {
        g_SufP[(size_t)NROW * DH + c] = sufBase - lp;
        g_PreQ[(size_t)NROW * DH + c] = preBase + lq;
    }
    if (c < CHUNK) {
        int m = cc * CHUNK + c;
        double bSp = g_chSp[cc], bSq = g_chSq[cc], stot = g_SpTot;
        g_SpSuf[m] = stot - (bSp + eP[c]);
        g_SqPre[m] = bSq + eQ[c];
        if (cc == NCHUNK - 1 && c == CHUNK - 1) {
            g_SpSuf[NROW] = stot - (bSp + eP[CHUNK]);
            g_SqPre[NROW] = bSq + eQ[CHUNK];
        }
    }
}

// ---------------- K6: att (268 MB stream, 32 rows/block) + coefs + fused out gather ----------------
__global__ void k_att(float* __restrict__ att, float* __restrict__ out,
                      const float* __restrict__ a_b) {
    __shared__ float sA[32], sB[32], sT[32];
    __shared__ int   sK[32];
    int jx = blockIdx.x, iy = blockIdx.y;
    int i0 = iy * 32;
    int tid = threadIdx.x;
    if (tid < 32) {
        int i = i0 + tid;
        float cb = __ldg(&a_b[0]);
        float s1 = G_S1[i];
        float s2m = ord2f(*G_MAXU);
        float u = s1 + cb + s2m;
        float m = u > 0.f ? u : SLOPE * u;          // exact row max of f(x)
        float alpha = expf(u - m);
        float beta  = expf(SLOPE * u - m);
        float t = -(s1 + cb);                       // x>0  <=>  s2[j] > t
        int lo = 0, hi = NROW;
        while (lo < hi) {
            int mid = (lo + hi) >> 1;
            if (g_s2s[mid] > t) hi = mid; else lo = mid + 1;
        }
        int k = lo;
        double Z = (double)alpha * g_SpSuf[k] + (double)beta * g_SqPre[k];
        float Zf = (float)Z;
        sA[tid] = alpha / Zf;
        sB[tid] = beta / Zf;
        sT[tid] = t;
        sK[tid] = k;
    }
    __syncthreads();
    if (jx == 0) {
        int c = tid;
#pragma unroll 4
        for (int r = 0; r < 32; r++) {
            int i = i0 + r;
            int k = sK[r];
            float v = sA[r] * g_SufP[(size_t)k * DH + c] + sB[r] * g_PreQ[(size_t)k * DH + c];
            out[(size_t)i * DH + c] = v > 0.f ? v : SLOPE * v;
        }
    }
    int j = jx * 1024 + tid * 4;
    float4 p = *(const float4*)&g_pj[j];
    float4 q = *(const float4*)&g_qj[j];
    float4 s = *(const float4*)&G_S2[j];
#pragma unroll 4
    for (int r = 0; r < 32; r++) {
        int i = i0 + r;
        float A = sA[r];
        float B = sB[r];
        float T = sT[r];
        float4 o;
        o.x = s.x > T ? A * p.x : B * q.x;
        o.y = s.y > T ? A * p.y : B * q.y;
        o.z = s.z > T ? A * p.z : B * q.z;
        o.w = s.w > T ? A * p.w : B * q.w;
        __stcs((float4*)&att[(size_t)i * NROW + j], o);
    }
}

// ---------------- launch ----------------
extern "C" void kernel_launch(void* const* d_in, const int* in_sizes, int n_in,
                              void* d_out, int out_size) {
    const float* doc = (const float*)d_in[0];
    const float* W   = (const float*)d_in[1];
    const float* Wb  = (const float*)d_in[2];
    const float* a   = (const float*)d_in[3];
    const float* ab  = (const float*)d_in[4];
    float* out = (float*)d_out;                  // [8192 x 256]
    float* att = out + (size_t)NROW * DH;        // [8192 x 8192]

    static void* zptr = nullptr;
    if (zptr == nullptr) cudaGetSymbolAddress(&zptr, g_zmem);
    cudaMemsetAsync(zptr, 0, Z_BYTES, 0);        // s1,s2,rank,done,s2max := 0

    k_gemm<<<dim3(NROW / 128, DH / 64), 256>>>(doc, W, Wb, a);
    k_ranksc<<<dim3(32, 16), 256>>>();
    k_chunk<<<NCHUNK, 256>>>();
    k_scan<<<2 * DH + 2, NCHUNK>>>();
    k_prefix<<<NCHUNK, 256>>>();
    k_att<<<dim3(NROW / 1024, NROW / 32), 256>>>(att, out, ab);
}